// round 13
// baseline (speedup 1.0000x reference)
#include <cuda_runtime.h>
#include <cstdint>
#include <math.h>

#define KK     15
#define HW     128
#define PLANE  16384
#define CIN    768
#define NSO    24
#define NF     48          // filters (N dim)
#define RT     3           // output rows per CTA
#define ARING  7           // TMEM A-chunk ring slots (16 cols each)
#define NCHUNK 17          // RT + 14 input rows per CTA
#define NROUND 15          // one dy per round

// ---- smem layout (bytes) for tcgen05 path ----
#define SM_TMEM   0
#define SM_MBAR   64                  // 15 mbarriers x 8B
#define SM_B      1024                // 4 B-slots x 6144B (48 rows x 128B, SW128)
#define SLOT_BF   6144
#define SM_X      (SM_B + 4*SLOT_BF)  // 25600: 17 x-rows x 128 floats
// tcgen05 path needs ~34304; fallback needs ~53100. occ-2: 2x53568 <= 228KB ok.
#define SMEM_GABOR 53568

// TMEM (256 cols/CTA): D tiles at r*48 (r=0..2, 144); A ring at 144 + slot*16
#define TM_A0  144
#define TM_DSTRIDE 48
#define TMEM_COLS 256

// idesc: dfmt=F32(1)<<4 | afmt=TF32(2)<<7 | bfmt=TF32(2)<<10 | (N/8)<<17 | (M/16)<<24
#define IDESC_TF32 ((1u<<4) | (2u<<7) | (2u<<10) | ((NF/8)<<17) | ((128/16)<<24))

#if defined(__CUDA_ARCH__) && (defined(__CUDA_ARCH_FEAT_SM103_ALL) || defined(__CUDA_ARCH_SPECIFIC__))
#define HAS_TCGEN05 1
#else
#define HAS_TCGEN05 0
#endif

typedef unsigned long long u64;

// Scratch (.bss)
__device__ float g_mag[(size_t)4 * CIN * PLANE];   // [b][c*24+so][y*128+x]
__device__ float g_z[(size_t)128 * PLANE];
__device__ float g_stats[256];

// ---------------- portable helpers ----------------
__device__ __forceinline__ u64 splat(float v) {
    u64 r; asm("mov.b64 %0, {%1,%1};" : "=l"(r) : "f"(v)); return r;
}
__device__ __forceinline__ void fma2(u64& d, u64 a, u64 b) {
    asm("fma.rn.f32x2 %0, %1, %2, %0;" : "+l"(d) : "l"(a), "l"(b));
}
__device__ __forceinline__ void upk2(u64 v, float& lo, float& hi) {
    asm("mov.b64 {%0,%1}, %2;" : "=f"(lo), "=f"(hi) : "l"(v));
}

#if HAS_TCGEN05
// ---------------- sm_103a-only helpers ----------------
__device__ __forceinline__ uint32_t smem_u32(const void* p) {
    uint32_t a;
    asm("{ .reg .u64 t; cvta.to.shared.u64 t, %1; cvt.u32.u64 %0, t; }" : "=r"(a) : "l"(p));
    return a;
}
__device__ __forceinline__ uint32_t elect1() {
    uint32_t p;
    asm volatile("{ .reg .pred p; elect.sync _|p, 0xFFFFFFFF; selp.b32 %0,1,0,p; }" : "=r"(p));
    return p;
}
__device__ __forceinline__ float tf32r(float v) {
    uint32_t r; asm("cvt.rna.tf32.f32 %0, %1;" : "=r"(r) : "f"(v));
    return __uint_as_float(r);
}
#define SWZ(o) ((o) ^ ((((uint32_t)(o)) >> 3) & 0x70))

static __device__ __forceinline__ uint64_t mkdesc(uint32_t addr) {
    const uint64_t base = (uint64_t(2) << 61) | (uint64_t(1) << 46)
                        | (uint64_t(64) << 32) | (uint64_t(1) << 16);  // SW128
    return base | ((uint64_t)(addr >> 4) & 0x3FFF);
}
__device__ __forceinline__ void tmem_alloc(uint32_t smem_addr, uint32_t ncols) {
    asm volatile("tcgen05.alloc.cta_group::1.sync.aligned.shared::cta.b32 [%0], %1;"
                 :: "r"(smem_addr), "r"(ncols) : "memory");
}
__device__ __forceinline__ void tmem_relinq() {
    asm volatile("tcgen05.relinquish_alloc_permit.cta_group::1.sync.aligned;");
}
__device__ __forceinline__ void tmem_dealloc(uint32_t tmem, uint32_t ncols) {
    asm volatile("tcgen05.dealloc.cta_group::1.sync.aligned.b32 %0, %1;" :: "r"(tmem), "r"(ncols));
}
__device__ __forceinline__ void mbar_init(uint32_t a, uint32_t cnt) {
    asm volatile("mbarrier.init.shared.b64 [%0], %1;" :: "r"(a), "r"(cnt) : "memory");
}
__device__ __forceinline__ void mbar_inval(uint32_t a) {
    asm volatile("mbarrier.inval.shared.b64 [%0];" :: "r"(a) : "memory");
}
__device__ __forceinline__ void mbar_wait(uint32_t a, uint32_t par) {
    uint32_t done;
    asm volatile("{ .reg .pred p; mbarrier.try_wait.parity.acquire.cta.shared::cta.b64 p, [%1], %2;"
                 " selp.b32 %0,1,0,p; }" : "=r"(done) : "r"(a), "r"(par) : "memory");
    if (!done) {
        asm volatile("{ .reg .pred P1; WL_%=: mbarrier.try_wait.parity.acquire.cta.shared::cta.b64 P1, [%0], %1, 0x989680;"
                     " @P1 bra.uni WD_%=; bra.uni WL_%=; WD_%=: }" :: "r"(a), "r"(par) : "memory");
    }
}
__device__ __forceinline__ void mma_commit(uint32_t mbar) {
    asm volatile("tcgen05.commit.cta_group::1.mbarrier::arrive::one.shared::cluster.b64 [%0];"
                 :: "r"(mbar) : "memory");
}
// TS form: A in TMEM, B via SMEM descriptor
__device__ __forceinline__ void mma_tf32_ts(uint32_t d, uint32_t a, uint64_t bd, uint32_t en) {
    asm volatile("{ .reg .pred p; setp.ne.u32 p, %4, 0;"
                 " tcgen05.mma.cta_group::1.kind::tf32 [%0], [%1], %2, %3, {%5,%5,%5,%5}, p; }"
                 :: "r"(d), "r"(a), "l"(bd), "r"(IDESC_TF32), "r"(en), "r"(0u) : "memory");
}
__device__ __forceinline__ void fence_async_shared() {
    asm volatile("fence.proxy.async.shared::cta;" ::: "memory");
}
__device__ __forceinline__ void tc_fence_before() {
    asm volatile("tcgen05.fence::before_thread_sync;" ::: "memory");
}
__device__ __forceinline__ void tc_fence_after() {
    asm volatile("tcgen05.fence::after_thread_sync;" ::: "memory");
}
__device__ __forceinline__ void tc_wait_st() {
    asm volatile("tcgen05.wait::st.sync.aligned;" ::: "memory");
}
__device__ __forceinline__ void tc_wait_ld() {
    asm volatile("tcgen05.wait::ld.sync.aligned;" ::: "memory");
}
__device__ __forceinline__ void sttm_x16(uint32_t a, const uint32_t* r) {
    asm volatile("tcgen05.st.sync.aligned.32x32b.x16.b32 [%0], "
        "{%1,%2,%3,%4,%5,%6,%7,%8,%9,%10,%11,%12,%13,%14,%15,%16};"
        :: "r"(a),
           "r"(r[0]),"r"(r[1]),"r"(r[2]),"r"(r[3]),"r"(r[4]),"r"(r[5]),"r"(r[6]),"r"(r[7]),
           "r"(r[8]),"r"(r[9]),"r"(r[10]),"r"(r[11]),"r"(r[12]),"r"(r[13]),"r"(r[14]),"r"(r[15])
        : "memory");
}
__device__ __forceinline__ void ldtm_x16(uint32_t* r, uint32_t a) {
    asm volatile("tcgen05.ld.sync.aligned.32x32b.x16.b32 "
        "{%0,%1,%2,%3,%4,%5,%6,%7,%8,%9,%10,%11,%12,%13,%14,%15}, [%16];"
        : "=r"(r[0]),"=r"(r[1]),"=r"(r[2]),"=r"(r[3]),"=r"(r[4]),"=r"(r[5]),"=r"(r[6]),"=r"(r[7]),
          "=r"(r[8]),"=r"(r[9]),"=r"(r[10]),"=r"(r[11]),"=r"(r[12]),"=r"(r[13]),"=r"(r[14]),"=r"(r[15])
        : "r"(a));
}

// im2col chunk builder: A rounded once to tf32 (hi only), 16 cols per chunk
__device__ __forceinline__ void build_chunk(char* smem, uint32_t tmem_a, int ci, int wid, int lid) {
    const float* xr = (const float*)(smem + SM_X) + ci * HW;
    const int xpos = (wid << 5) + lid;
    uint32_t regs[16];
#pragma unroll
    for (int dx = 0; dx < 16; ++dx) {
        int sx = xpos + dx - 7;
        float v = (dx < 15 && sx >= 0 && sx < HW) ? xr[sx] : 0.f;
        regs[dx] = __float_as_uint(tf32r(v));
    }
    sttm_x16(tmem_a + ((uint32_t)wid << 21), regs);
}
// Filters for one dy into SMEM (SW128): cols 0-15 hi(tf32), 16-31 lo(residual tf32)
__device__ __forceinline__ void build_filt(char* smem, int boff, const float* __restrict__ filters,
                                           int dy, int t) {
    for (int i = t; i < NF * 32; i += 128) {
        int f = i >> 5, col = i & 31, dx = col & 15;
        float v = (dx < 15) ? filters[(f >> 1) * 450 + (f & 1) * 225 + dy * 15 + dx] : 0.f;
        float hi = tf32r(v);
        float val = (col >= 16) ? tf32r(v - hi) : hi;
        *(float*)(smem + boff + SWZ(f * 128 + col * 4)) = val;
    }
}
#endif  // HAS_TCGEN05

// ---------------------------------------------------------------------------
// Kernel A: Gabor conv + magnitude.
// sm_103a: tcgen05 tf32 TS-mode implicit GEMM, 2-term D = Ahi x (Bhi+Blo).
// 256-col TMEM per CTA -> TWO CTAs co-resident per SM (latency chains overlap).
// RT=3, ring-7 A (build lead +4), depth-3 per-dy rounds, 4 B slots.
// grid (43 row-groups, 128 planes), 256 threads, occ 2
// ---------------------------------------------------------------------------
__global__ __launch_bounds__(256, 2)
void gabor_mma_kernel(const float* __restrict__ x, const float* __restrict__ filters) {
#if HAS_TCGEN05
    extern __shared__ char smem[];
    const uint32_t sb = smem_u32(smem);
    const int tid = threadIdx.x, wid = tid >> 5, lid = tid & 31;
    const int plane = blockIdx.y;
    const int y0 = blockIdx.x * RT;
    const int b = plane >> 5, c = plane & 31;

    // stage x rows + mbar init BEFORE tmem_alloc (overlaps peer CTA's tenure)
    const float* xp = x + (size_t)plane * PLANE;
    float* xs = (float*)(smem + SM_X);
    for (int i = tid; i < NCHUNK * HW; i += 256) {
        int rr = i >> 7, cc = i & 127;
        int gy = y0 + rr - 7;
        xs[i] = (gy >= 0 && gy < HW) ? xp[gy * HW + cc] : 0.f;
    }
    if (tid == 0)
        for (int i = 0; i < NROUND; ++i) mbar_init(sb + SM_MBAR + i * 8, 1);
    __syncthreads();

    if (wid == 0) tmem_alloc(sb + SM_TMEM, TMEM_COLS);
    __syncthreads();
    uint32_t tmem;
    asm volatile("ld.shared.b32 %0, [%1];" : "=r"(tmem) : "r"(sb + SM_TMEM));
    if (wid == 0) tmem_relinq();

    // prebuild A chunks 0..6 into ring slots 0..6 (covers rounds 0..4)
    if (wid < 4) {
        for (int ci = 0; ci < ARING; ++ci)
            build_chunk(smem, tmem + TM_A0 + ci * 16, ci, wid, lid);
        tc_wait_st();
    }

    for (int rd = 0; rd < NROUND; ++rd) {
        // depth-3: chunk rd+4 overwrites chunk rd-3 (slot (rd+4)%7); B slot rd&3
        // reuse overwrites dy=rd-4. Both guarded by wait(rd-3).
        if (rd >= 3) mbar_wait(sb + SM_MBAR + (rd - 3) * 8, 0);
        if (wid < 4) {
            int ci = rd + 4;
            if (ci >= ARING && ci < NCHUNK) {
                build_chunk(smem, tmem + TM_A0 + (ci % ARING) * 16, ci, wid, lid);
                tc_wait_st();
            }
        } else {
            build_filt(smem, SM_B + (rd & 3) * SLOT_BF, filters, rd, tid - 128);
        }
        tc_fence_before();
        fence_async_shared();
        __syncthreads();
        if (wid == 0) {
            tc_fence_after();
            if (elect1()) {
                uint64_t bd = mkdesc(sb + SM_B + (rd & 3) * SLOT_BF);
#pragma unroll
                for (int r = 0; r < RT; ++r) {
                    uint32_t a = tmem + TM_A0 + ((rd + r) % ARING) * 16;
                    uint32_t d = tmem + r * TM_DSTRIDE;
                    mma_tf32_ts(d, a + 0, bd + 0, rd > 0);  // Ahi x Bhi, k0
                    mma_tf32_ts(d, a + 8, bd + 2, 1);       // Ahi x Bhi, k1
                    mma_tf32_ts(d, a + 0, bd + 4, 1);       // Ahi x Blo, k0
                    mma_tf32_ts(d, a + 8, bd + 6, 1);       // Ahi x Blo, k1
                }
                mma_commit(sb + SM_MBAR + rd * 8);
            }
        }
    }
    mbar_wait(sb + SM_MBAR + (NROUND - 1) * 8, 0);
    tc_fence_after();

    // epilogue: warp-group 0 -> tiles 0,2 ; warp-group 1 -> tile 1
    const int sub = wid & 3;
    const int xc = sub * 32 + lid;
    const size_t mbase = ((size_t)b * CIN + (size_t)c * NSO) * PLANE + xc;
#pragma unroll
    for (int rr = 0; rr < 2; ++rr) {
        const int r = (wid >> 2) + rr * 2;   // 0,2 | 1,3
        if (r >= RT) break;
        const int y = y0 + r;
        uint32_t rg[48];
        ldtm_x16(rg,      tmem + r * TM_DSTRIDE);
        ldtm_x16(rg + 16, tmem + r * TM_DSTRIDE + 16);
        ldtm_x16(rg + 32, tmem + r * TM_DSTRIDE + 32);
        tc_wait_ld();
        if (y < HW) {
#pragma unroll
            for (int s = 0; s < NSO; ++s) {
                float re = __uint_as_float(rg[2 * s]);
                float im = __uint_as_float(rg[2 * s + 1]);
                g_mag[mbase + (size_t)s * PLANE + (size_t)y * HW] = sqrtf(re * re + im * im);
            }
        }
    }
    __syncthreads();
    if (tid == 0)
        for (int i = 0; i < NROUND; ++i) mbar_inval(sb + SM_MBAR + i * 8);
    __syncthreads();
    if (wid == 0) tmem_dealloc(tmem, TMEM_COLS);

#else  // ---------------- scalar FFMA2 fallback (non-arch-specific pass) -----
    extern __shared__ float smf[];
    float* fs = smf;                        // [225][48]
    float* xs = smf + 225 * NF;             // [17][144]
    const int XW = 144;
    const int tid = threadIdx.x;
    const int plane = blockIdx.y;
    const int y0 = blockIdx.x * RT;
    const int b = plane >> 5, c = plane & 31;

    for (int i = tid; i < 225 * NF; i += 256) {
        int tap = i / NF, f = i - tap * NF;
        fs[i] = filters[(f >> 1) * 450 + (f & 1) * 225 + tap];
    }
    const float* xp = x + (size_t)plane * PLANE;
    for (int i = tid; i < NCHUNK * XW; i += 256) {
        int rr = i / XW, cc = i - rr * XW;
        int gy = y0 + rr - 7, gx = cc - 7;
        xs[i] = (gy >= 0 && gy < HW && gx >= 0 && gx < HW) ? xp[gy * HW + gx] : 0.f;
    }
    __syncthreads();

    const int x0 = (tid & 63) * 2;
    const int ry = tid >> 6;                 // 0..3; ry==3 idle
    const int y = y0 + ry;
    if (ry < RT && y < HW) {
        const size_t mbase0 = ((size_t)b * CIN + (size_t)c * NSO) * PLANE
                            + (size_t)y * HW + x0;
        for (int g = 0; g < 4; ++g) {
            u64 acc[2][6];
#pragma unroll
            for (int p = 0; p < 2; ++p)
#pragma unroll
                for (int s = 0; s < 6; ++s) acc[p][s] = 0ull;
            for (int dy = 0; dy < KK; ++dy) {
                const float* xr = xs + (ry + dy) * XW + x0;
                const float* wr = fs + dy * KK * NF + g * 12;
#pragma unroll
                for (int dx = 0; dx < KK; ++dx) {
                    const float* w = wr + dx * NF;
                    ulonglong2 wa = *(const ulonglong2*)(w);
                    ulonglong2 wb = *(const ulonglong2*)(w + 4);
                    ulonglong2 wc = *(const ulonglong2*)(w + 8);
                    u64 wp[6] = {wa.x, wa.y, wb.x, wb.y, wc.x, wc.y};
                    u64 xv[2] = {splat(xr[dx]), splat(xr[dx + 1])};
#pragma unroll
                    for (int p = 0; p < 2; ++p)
#pragma unroll
                        for (int s = 0; s < 6; ++s) fma2(acc[p][s], xv[p], wp[s]);
                }
            }
#pragma unroll
            for (int s = 0; s < 6; ++s) {
                float re0, im0, re1, im1;
                upk2(acc[0][s], re0, im0);
                upk2(acc[1][s], re1, im1);
                float2 m = make_float2(sqrtf(re0*re0 + im0*im0), sqrtf(re1*re1 + im1*im1));
                *(float2*)(g_mag + mbase0 + (size_t)(g * 6 + s) * PLANE) = m;
            }
        }
    }
#endif
}

// ---------------------------------------------------------------------------
// Kernel B: channel mix (FFMA2), bias dropped (cancels in instance norm)
// ---------------------------------------------------------------------------
static const int SMEM_MIX = CIN * 32 * 4;

__global__ __launch_bounds__(256, 2)
void mix_kernel(const float* __restrict__ w1) {
    extern __shared__ float w1s[];
    const int tid = threadIdx.x;
    for (int i = tid; i < CIN * 32; i += 256) {
        int j = i >> 5, o = i & 31;
        w1s[i] = w1[o * CIN + j];
    }
    __syncthreads();

    const int bb = blockIdx.y;
    const int q0 = blockIdx.x * 512 + tid * 2;
    const float* mp = g_mag + (size_t)bb * CIN * PLANE + q0;

    u64 acc[16][2];
#pragma unroll
    for (int op = 0; op < 16; ++op) { acc[op][0] = 0ull; acc[op][1] = 0ull; }

#pragma unroll 4
    for (int j = 0; j < CIN; ++j) {
        float2 m = *(const float2*)(mp + (size_t)j * PLANE);
        u64 mx = splat(m.x), my = splat(m.y);
        const ulonglong2* wrow = (const ulonglong2*)(w1s + j * 32);
#pragma unroll
        for (int q4 = 0; q4 < 8; ++q4) {
            ulonglong2 w2 = wrow[q4];
            fma2(acc[q4 * 2 + 0][0], mx, w2.x);
            fma2(acc[q4 * 2 + 0][1], my, w2.x);
            fma2(acc[q4 * 2 + 1][0], mx, w2.y);
            fma2(acc[q4 * 2 + 1][1], my, w2.y);
        }
    }
#pragma unroll
    for (int op = 0; op < 16; ++op) {
        float a0lo, a0hi, a1lo, a1hi;
        upk2(acc[op][0], a0lo, a0hi);
        upk2(acc[op][1], a1lo, a1hi);
        *(float2*)(g_z + (size_t)(bb * 32 + 2 * op)     * PLANE + q0) = make_float2(a0lo, a1lo);
        *(float2*)(g_z + (size_t)(bb * 32 + 2 * op + 1) * PLANE + q0) = make_float2(a0hi, a1hi);
    }
}

// ---------------------------------------------------------------------------
__global__ void stats_kernel() {
    const int plane = blockIdx.x;
    const float* zp = g_z + (size_t)plane * PLANE;
    const int tid = threadIdx.x;
    float s = 0.f, s2 = 0.f;
    for (int i = tid * 4; i < PLANE; i += 1024) {
        float4 v = *(const float4*)(zp + i);
        s  += v.x + v.y + v.z + v.w;
        s2 += v.x * v.x + v.y * v.y + v.z * v.z + v.w * v.w;
    }
    __shared__ float r1[256], r2[256];
    r1[tid] = s; r2[tid] = s2;
    __syncthreads();
    for (int st = 128; st > 0; st >>= 1) {
        if (tid < st) { r1[tid] += r1[tid + st]; r2[tid] += r2[tid + st]; }
        __syncthreads();
    }
    if (tid == 0) {
        float mean = r1[0] * (1.f / PLANE);
        float var  = r2[0] * (1.f / PLANE) - mean * mean;
        g_stats[plane * 2]     = mean;
        g_stats[plane * 2 + 1] = rsqrtf(var + 1e-5f);
    }
}

__global__ void norm_kernel(float* __restrict__ out) {
    __shared__ float s[32][33];
    const int plane = blockIdx.y;
    const int tile  = blockIdx.x;
    const int hb = (tile >> 2) * 32, wb = (tile & 3) * 32;
    const float mean = g_stats[plane * 2];
    const float rstd = g_stats[plane * 2 + 1];
    const float* zp = g_z + (size_t)plane * PLANE;
    float* op = out + (size_t)plane * PLANE;
    const int cc = threadIdx.x & 31;
    const int r0 = threadIdx.x >> 5;
#pragma unroll
    for (int k = 0; k < 4; ++k) {
        int rr = r0 + k * 8;
        s[rr][cc] = zp[(wb + rr) * HW + hb + cc];
    }
    __syncthreads();
#pragma unroll
    for (int k = 0; k < 4; ++k) {
        int rr = r0 + k * 8;
        op[(hb + rr) * HW + wb + cc] = (s[cc][rr] - mean) * rstd;
    }
}

// ---------------------------------------------------------------------------
extern "C" void kernel_launch(void* const* d_in, const int* in_sizes, int n_in,
                              void* d_out, int out_size) {
    const float* x       = (const float*)d_in[0];
    const float* filters = (const float*)d_in[1];
    const float* w1      = (const float*)d_in[2];
    float* out = (float*)d_out;

    cudaFuncSetAttribute(gabor_mma_kernel, cudaFuncAttributeMaxDynamicSharedMemorySize, SMEM_GABOR);
    cudaFuncSetAttribute(mix_kernel,       cudaFuncAttributeMaxDynamicSharedMemorySize, SMEM_MIX);

    gabor_mma_kernel<<<dim3((HW + RT - 1) / RT, 128), 256, SMEM_GABOR>>>(x, filters);
    mix_kernel<<<dim3(32, 4), 256, SMEM_MIX>>>(w1);
    stats_kernel<<<128, 256>>>();
    norm_kernel<<<dim3(16, 128), 256>>>(out);
}

// round 14
// speedup vs baseline: 1.2602x; 1.2602x over previous
#include <cuda_runtime.h>
#include <cstdint>
#include <math.h>

#define KK     15
#define HW     128
#define PLANE  16384
#define CIN    768
#define NSO    24
#define NF     48          // filters (N dim)
#define RT     4           // output rows per CTA
#define NCHUNK 18          // RT + 14 input rows per CTA

// ---- smem layout (bytes) for tcgen05 path ----
#define SM_TMEM   0
#define SM_MBAR   64                  // 1 mbarrier
#define SM_B      1024                // 15 B-slots x 6144B (48 rows x 128B, SW128)
#define SLOT_BF   6144
#define SM_X      (SM_B + 15*SLOT_BF) // 93184: 18 x-rows x 128 floats
#define SMEM_GABOR 102528             // (fallback needs 53568)

// TMEM columns: D tiles at r*48 (r=0..3, 192); A chunks at 192 + ci*16 (288)
#define TM_A0  192
#define TM_DSTRIDE 48

// idesc: dfmt=F32(1)<<4 | afmt=TF32(2)<<7 | bfmt=TF32(2)<<10 | (N/8)<<17 | (M/16)<<24
#define IDESC_TF32 ((1u<<4) | (2u<<7) | (2u<<10) | ((NF/8)<<17) | ((128/16)<<24))

#if defined(__CUDA_ARCH__) && (defined(__CUDA_ARCH_FEAT_SM103_ALL) || defined(__CUDA_ARCH_SPECIFIC__))
#define HAS_TCGEN05 1
#else
#define HAS_TCGEN05 0
#endif

typedef unsigned long long u64;

// Scratch (.bss)
__device__ float g_mag[(size_t)4 * CIN * PLANE];   // [b][c*24+so][y*128+x]
__device__ float g_z[(size_t)128 * PLANE];
__device__ float g_stats[256];

// ---------------- portable helpers ----------------
__device__ __forceinline__ u64 splat(float v) {
    u64 r; asm("mov.b64 %0, {%1,%1};" : "=l"(r) : "f"(v)); return r;
}
__device__ __forceinline__ void fma2(u64& d, u64 a, u64 b) {
    asm("fma.rn.f32x2 %0, %1, %2, %0;" : "+l"(d) : "l"(a), "l"(b));
}
__device__ __forceinline__ void upk2(u64 v, float& lo, float& hi) {
    asm("mov.b64 {%0,%1}, %2;" : "=f"(lo), "=f"(hi) : "l"(v));
}

#if HAS_TCGEN05
// ---------------- sm_103a-only helpers ----------------
__device__ __forceinline__ uint32_t smem_u32(const void* p) {
    uint32_t a;
    asm("{ .reg .u64 t; cvta.to.shared.u64 t, %1; cvt.u32.u64 %0, t; }" : "=r"(a) : "l"(p));
    return a;
}
__device__ __forceinline__ uint32_t elect1() {
    uint32_t p;
    asm volatile("{ .reg .pred p; elect.sync _|p, 0xFFFFFFFF; selp.b32 %0,1,0,p; }" : "=r"(p));
    return p;
}
__device__ __forceinline__ float tf32r(float v) {
    uint32_t r; asm("cvt.rna.tf32.f32 %0, %1;" : "=r"(r) : "f"(v));
    return __uint_as_float(r);
}
#define SWZ(o) ((o) ^ ((((uint32_t)(o)) >> 3) & 0x70))

static __device__ __forceinline__ uint64_t mkdesc(uint32_t addr) {
    const uint64_t base = (uint64_t(2) << 61) | (uint64_t(1) << 46)
                        | (uint64_t(64) << 32) | (uint64_t(1) << 16);  // SW128
    return base | ((uint64_t)(addr >> 4) & 0x3FFF);
}
__device__ __forceinline__ void tmem_alloc(uint32_t smem_addr, uint32_t ncols) {
    asm volatile("tcgen05.alloc.cta_group::1.sync.aligned.shared::cta.b32 [%0], %1;"
                 :: "r"(smem_addr), "r"(ncols) : "memory");
}
__device__ __forceinline__ void tmem_relinq() {
    asm volatile("tcgen05.relinquish_alloc_permit.cta_group::1.sync.aligned;");
}
__device__ __forceinline__ void tmem_dealloc(uint32_t tmem, uint32_t ncols) {
    asm volatile("tcgen05.dealloc.cta_group::1.sync.aligned.b32 %0, %1;" :: "r"(tmem), "r"(ncols));
}
__device__ __forceinline__ void mbar_init(uint32_t a, uint32_t cnt) {
    asm volatile("mbarrier.init.shared.b64 [%0], %1;" :: "r"(a), "r"(cnt) : "memory");
}
__device__ __forceinline__ void mbar_inval(uint32_t a) {
    asm volatile("mbarrier.inval.shared.b64 [%0];" :: "r"(a) : "memory");
}
__device__ __forceinline__ void mbar_wait(uint32_t a, uint32_t par) {
    uint32_t done;
    asm volatile("{ .reg .pred p; mbarrier.try_wait.parity.acquire.cta.shared::cta.b64 p, [%1], %2;"
                 " selp.b32 %0,1,0,p; }" : "=r"(done) : "r"(a), "r"(par) : "memory");
    if (!done) {
        asm volatile("{ .reg .pred P1; WL_%=: mbarrier.try_wait.parity.acquire.cta.shared::cta.b64 P1, [%0], %1, 0x989680;"
                     " @P1 bra.uni WD_%=; bra.uni WL_%=; WD_%=: }" :: "r"(a), "r"(par) : "memory");
    }
}
__device__ __forceinline__ void mma_commit(uint32_t mbar) {
    asm volatile("tcgen05.commit.cta_group::1.mbarrier::arrive::one.shared::cluster.b64 [%0];"
                 :: "r"(mbar) : "memory");
}
// TS form: A in TMEM, B via SMEM descriptor
__device__ __forceinline__ void mma_tf32_ts(uint32_t d, uint32_t a, uint64_t bd, uint32_t en) {
    asm volatile("{ .reg .pred p; setp.ne.u32 p, %4, 0;"
                 " tcgen05.mma.cta_group::1.kind::tf32 [%0], [%1], %2, %3, {%5,%5,%5,%5}, p; }"
                 :: "r"(d), "r"(a), "l"(bd), "r"(IDESC_TF32), "r"(en), "r"(0u) : "memory");
}
__device__ __forceinline__ void fence_async_shared() {
    asm volatile("fence.proxy.async.shared::cta;" ::: "memory");
}
__device__ __forceinline__ void tc_fence_before() {
    asm volatile("tcgen05.fence::before_thread_sync;" ::: "memory");
}
__device__ __forceinline__ void tc_fence_after() {
    asm volatile("tcgen05.fence::after_thread_sync;" ::: "memory");
}
__device__ __forceinline__ void tc_wait_st() {
    asm volatile("tcgen05.wait::st.sync.aligned;" ::: "memory");
}
__device__ __forceinline__ void tc_wait_ld() {
    asm volatile("tcgen05.wait::ld.sync.aligned;" ::: "memory");
}
__device__ __forceinline__ void sttm_x16(uint32_t a, const uint32_t* r) {
    asm volatile("tcgen05.st.sync.aligned.32x32b.x16.b32 [%0], "
        "{%1,%2,%3,%4,%5,%6,%7,%8,%9,%10,%11,%12,%13,%14,%15,%16};"
        :: "r"(a),
           "r"(r[0]),"r"(r[1]),"r"(r[2]),"r"(r[3]),"r"(r[4]),"r"(r[5]),"r"(r[6]),"r"(r[7]),
           "r"(r[8]),"r"(r[9]),"r"(r[10]),"r"(r[11]),"r"(r[12]),"r"(r[13]),"r"(r[14]),"r"(r[15])
        : "memory");
}
__device__ __forceinline__ void ldtm_x16(uint32_t* r, uint32_t a) {
    asm volatile("tcgen05.ld.sync.aligned.32x32b.x16.b32 "
        "{%0,%1,%2,%3,%4,%5,%6,%7,%8,%9,%10,%11,%12,%13,%14,%15}, [%16];"
        : "=r"(r[0]),"=r"(r[1]),"=r"(r[2]),"=r"(r[3]),"=r"(r[4]),"=r"(r[5]),"=r"(r[6]),"=r"(r[7]),
          "=r"(r[8]),"=r"(r[9]),"=r"(r[10]),"=r"(r[11]),"=r"(r[12]),"=r"(r[13]),"=r"(r[14]),"=r"(r[15])
        : "r"(a));
}

// im2col chunk builder: A rounded once to tf32 (hi only), 16 cols per chunk
__device__ __forceinline__ void build_chunk(char* smem, uint32_t tmem_a, int ci, int wid, int lid) {
    const float* xr = (const float*)(smem + SM_X) + ci * HW;
    const int xpos = (wid << 5) + lid;
    uint32_t regs[16];
#pragma unroll
    for (int dx = 0; dx < 16; ++dx) {
        int sx = xpos + dx - 7;
        float v = (dx < 15 && sx >= 0 && sx < HW) ? xr[sx] : 0.f;
        regs[dx] = __float_as_uint(tf32r(v));
    }
    sttm_x16(tmem_a + ((uint32_t)wid << 21), regs);
}
// Filters for one dy into SMEM (SW128): cols 0-15 hi(tf32), 16-31 lo(residual tf32)
__device__ __forceinline__ void build_filt(char* smem, int boff, const float* __restrict__ filters,
                                           int dy, int t) {
    for (int i = t; i < NF * 32; i += 128) {
        int f = i >> 5, col = i & 31, dx = col & 15;
        float v = (dx < 15) ? filters[(f >> 1) * 450 + (f & 1) * 225 + dy * 15 + dx] : 0.f;
        float hi = tf32r(v);
        float val = (col >= 16) ? tf32r(v - hi) : hi;
        *(float*)(smem + boff + SWZ(f * 128 + col * 4)) = val;
    }
}
#endif  // HAS_TCGEN05

// ---------------------------------------------------------------------------
// Kernel A: Gabor conv + magnitude.
// sm_103a: tcgen05 tf32 TS-mode implicit GEMM, 2-term split D = Ahi x (Bhi+Blo).
// SINGLE ROUND (R12 base). MMA issue reordered for operand locality:
// per dy: b0 fwd r0->r3 (a+0), b4 rev r3->r0 (a+0), b2 fwd (a+8), b6 rev (a+8)
// -> adjacent dispatches share the A TMEM segment and/or B SMEM segment.
// grid (32 row-groups, 128 planes), 256 threads, occ 1
// ---------------------------------------------------------------------------
__global__ __launch_bounds__(256, 1)
void gabor_mma_kernel(const float* __restrict__ x, const float* __restrict__ filters) {
#if HAS_TCGEN05
    extern __shared__ char smem[];
    const uint32_t sb = smem_u32(smem);
    const int tid = threadIdx.x, wid = tid >> 5, lid = tid & 31;
    const int plane = blockIdx.y;
    const int y0 = blockIdx.x * RT;
    const int b = plane >> 5, c = plane & 31;

    // stage x + mbar init + B builds BEFORE tmem_alloc
    const float* xp = x + (size_t)plane * PLANE;
    float* xs = (float*)(smem + SM_X);
    for (int i = tid; i < NCHUNK * HW; i += 256) {
        int rr = i >> 7, cc = i & 127;
        int gy = y0 + rr - 7;
        xs[i] = (gy >= 0 && gy < HW) ? xp[gy * HW + cc] : 0.f;
    }
    if (tid == 0) mbar_init(sb + SM_MBAR, 1);
    if (wid >= 4)
        for (int dy = 0; dy < KK; ++dy)
            build_filt(smem, SM_B + dy * SLOT_BF, filters, dy, tid - 128);
    __syncthreads();

    if (wid == 0) tmem_alloc(sb + SM_TMEM, 512);
    __syncthreads();
    uint32_t tmem;
    asm volatile("ld.shared.b32 %0, [%1];" : "=r"(tmem) : "r"(sb + SM_TMEM));
    if (wid == 0) tmem_relinq();

    // build ALL 18 A chunks into TMEM (warps 0-3)
    if (wid < 4) {
        for (int ci = 0; ci < NCHUNK; ++ci)
            build_chunk(smem, tmem + TM_A0 + ci * 16, ci, wid, lid);
        tc_wait_st();
    }
    tc_fence_before();
    fence_async_shared();
    __syncthreads();

    // single issue burst: 240 MMAs, operand-locality zigzag, one commit
    if (wid == 0) {
        tc_fence_after();
        if (elect1()) {
            for (int dy = 0; dy < KK; ++dy) {
                uint64_t bd = mkdesc(sb + SM_B + dy * SLOT_BF);
                // pass 1: Bhi k0 (bd+0), A k0 (a+0), r forward  [en=0 first touch]
#pragma unroll
                for (int r = 0; r < RT; ++r)
                    mma_tf32_ts(tmem + r * TM_DSTRIDE,
                                tmem + TM_A0 + (dy + r) * 16 + 0, bd + 0, dy > 0);
                // pass 2: Blo k0 (bd+4), A k0 (a+0), r reverse  [A r3 seg reused]
#pragma unroll
                for (int r = RT - 1; r >= 0; --r)
                    mma_tf32_ts(tmem + r * TM_DSTRIDE,
                                tmem + TM_A0 + (dy + r) * 16 + 0, bd + 4, 1);
                // pass 3: Bhi k1 (bd+2), A k1 (a+8), r forward
#pragma unroll
                for (int r = 0; r < RT; ++r)
                    mma_tf32_ts(tmem + r * TM_DSTRIDE,
                                tmem + TM_A0 + (dy + r) * 16 + 8, bd + 2, 1);
                // pass 4: Blo k1 (bd+6), A k1 (a+8), r reverse
#pragma unroll
                for (int r = RT - 1; r >= 0; --r)
                    mma_tf32_ts(tmem + r * TM_DSTRIDE,
                                tmem + TM_A0 + (dy + r) * 16 + 8, bd + 6, 1);
            }
            mma_commit(sb + SM_MBAR);
        }
    }
    mbar_wait(sb + SM_MBAR, 0);
    tc_fence_after();

    // epilogue: warps 0-3 -> tiles 0,1 ; warps 4-7 -> tiles 2,3 ; sub = wid&3
    const int sub = wid & 3;
    const int xc = sub * 32 + lid;
    const size_t mbase = ((size_t)b * CIN + (size_t)c * NSO) * PLANE + xc;
#pragma unroll
    for (int rr = 0; rr < 2; ++rr) {
        const int r = (wid >> 2) * 2 + rr;
        uint32_t rg[48];
        ldtm_x16(rg,      tmem + r * TM_DSTRIDE);
        ldtm_x16(rg + 16, tmem + r * TM_DSTRIDE + 16);
        ldtm_x16(rg + 32, tmem + r * TM_DSTRIDE + 32);
        tc_wait_ld();
        const int y = y0 + r;
#pragma unroll
        for (int s = 0; s < NSO; ++s) {
            float re = __uint_as_float(rg[2 * s]);
            float im = __uint_as_float(rg[2 * s + 1]);
            g_mag[mbase + (size_t)s * PLANE + (size_t)y * HW] = sqrtf(re * re + im * im);
        }
    }
    __syncthreads();
    if (tid == 0) mbar_inval(sb + SM_MBAR);
    __syncthreads();
    if (wid == 0) tmem_dealloc(tmem, 512);

#else  // ---------------- scalar FFMA2 fallback (non-arch-specific pass) -----
    extern __shared__ float smf[];
    float* fs = smf;                        // [225][48]
    float* xs = smf + 225 * NF;             // [18][144]
    const int XW = 144;
    const int tid = threadIdx.x;
    const int plane = blockIdx.y;
    const int y0 = blockIdx.x * RT;
    const int b = plane >> 5, c = plane & 31;

    for (int i = tid; i < 225 * NF; i += 256) {
        int tap = i / NF, f = i - tap * NF;
        fs[i] = filters[(f >> 1) * 450 + (f & 1) * 225 + tap];
    }
    const float* xp = x + (size_t)plane * PLANE;
    for (int i = tid; i < NCHUNK * XW; i += 256) {
        int rr = i / XW, cc = i - rr * XW;
        int gy = y0 + rr - 7, gx = cc - 7;
        xs[i] = (gy >= 0 && gy < HW && gx >= 0 && gx < HW) ? xp[gy * HW + gx] : 0.f;
    }
    __syncthreads();

    const int x0 = (tid & 63) * 2;
    const int ry = tid >> 6;
    const size_t mbase0 = ((size_t)b * CIN + (size_t)c * NSO) * PLANE
                        + (size_t)(y0 + ry) * HW + x0;
    for (int g = 0; g < 4; ++g) {
        u64 acc[2][6];
#pragma unroll
        for (int p = 0; p < 2; ++p)
#pragma unroll
            for (int s = 0; s < 6; ++s) acc[p][s] = 0ull;
        for (int dy = 0; dy < KK; ++dy) {
            const float* xr = xs + (ry + dy) * XW + x0;
            const float* wr = fs + dy * KK * NF + g * 12;
#pragma unroll
            for (int dx = 0; dx < KK; ++dx) {
                const float* w = wr + dx * NF;
                ulonglong2 wa = *(const ulonglong2*)(w);
                ulonglong2 wb = *(const ulonglong2*)(w + 4);
                ulonglong2 wc = *(const ulonglong2*)(w + 8);
                u64 wp[6] = {wa.x, wa.y, wb.x, wb.y, wc.x, wc.y};
                u64 xv[2] = {splat(xr[dx]), splat(xr[dx + 1])};
#pragma unroll
                for (int p = 0; p < 2; ++p)
#pragma unroll
                    for (int s = 0; s < 6; ++s) fma2(acc[p][s], xv[p], wp[s]);
            }
        }
#pragma unroll
        for (int s = 0; s < 6; ++s) {
            float re0, im0, re1, im1;
            upk2(acc[0][s], re0, im0);
            upk2(acc[1][s], re1, im1);
            float2 m = make_float2(sqrtf(re0*re0 + im0*im0), sqrtf(re1*re1 + im1*im1));
            *(float2*)(g_mag + mbase0 + (size_t)(g * 6 + s) * PLANE) = m;
        }
    }
#endif
}

// ---------------------------------------------------------------------------
// Kernel B: channel mix (FFMA2), bias dropped (cancels in instance norm)
// ---------------------------------------------------------------------------
static const int SMEM_MIX = CIN * 32 * 4;

__global__ __launch_bounds__(256, 2)
void mix_kernel(const float* __restrict__ w1) {
    extern __shared__ float w1s[];
    const int tid = threadIdx.x;
    for (int i = tid; i < CIN * 32; i += 256) {
        int j = i >> 5, o = i & 31;
        w1s[i] = w1[o * CIN + j];
    }
    __syncthreads();

    const int bb = blockIdx.y;
    const int q0 = blockIdx.x * 512 + tid * 2;
    const float* mp = g_mag + (size_t)bb * CIN * PLANE + q0;

    u64 acc[16][2];
#pragma unroll
    for (int op = 0; op < 16; ++op) { acc[op][0] = 0ull; acc[op][1] = 0ull; }

#pragma unroll 4
    for (int j = 0; j < CIN; ++j) {
        float2 m = *(const float2*)(mp + (size_t)j * PLANE);
        u64 mx = splat(m.x), my = splat(m.y);
        const ulonglong2* wrow = (const ulonglong2*)(w1s + j * 32);
#pragma unroll
        for (int q4 = 0; q4 < 8; ++q4) {
            ulonglong2 w2 = wrow[q4];
            fma2(acc[q4 * 2 + 0][0], mx, w2.x);
            fma2(acc[q4 * 2 + 0][1], my, w2.x);
            fma2(acc[q4 * 2 + 1][0], mx, w2.y);
            fma2(acc[q4 * 2 + 1][1], my, w2.y);
        }
    }
#pragma unroll
    for (int op = 0; op < 16; ++op) {
        float a0lo, a0hi, a1lo, a1hi;
        upk2(acc[op][0], a0lo, a0hi);
        upk2(acc[op][1], a1lo, a1hi);
        *(float2*)(g_z + (size_t)(bb * 32 + 2 * op)     * PLANE + q0) = make_float2(a0lo, a1lo);
        *(float2*)(g_z + (size_t)(bb * 32 + 2 * op + 1) * PLANE + q0) = make_float2(a0hi, a1hi);
    }
}

// ---------------------------------------------------------------------------
__global__ void stats_kernel() {
    const int plane = blockIdx.x;
    const float* zp = g_z + (size_t)plane * PLANE;
    const int tid = threadIdx.x;
    float s = 0.f, s2 = 0.f;
    for (int i = tid * 4; i < PLANE; i += 1024) {
        float4 v = *(const float4*)(zp + i);
        s  += v.x + v.y + v.z + v.w;
        s2 += v.x * v.x + v.y * v.y + v.z * v.z + v.w * v.w;
    }
    __shared__ float r1[256], r2[256];
    r1[tid] = s; r2[tid] = s2;
    __syncthreads();
    for (int st = 128; st > 0; st >>= 1) {
        if (tid < st) { r1[tid] += r1[tid + st]; r2[tid] += r2[tid + st]; }
        __syncthreads();
    }
    if (tid == 0) {
        float mean = r1[0] * (1.f / PLANE);
        float var  = r2[0] * (1.f / PLANE) - mean * mean;
        g_stats[plane * 2]     = mean;
        g_stats[plane * 2 + 1] = rsqrtf(var + 1e-5f);
    }
}

__global__ void norm_kernel(float* __restrict__ out) {
    __shared__ float s[32][33];
    const int plane = blockIdx.y;
    const int tile  = blockIdx.x;
    const int hb = (tile >> 2) * 32, wb = (tile & 3) * 32;
    const float mean = g_stats[plane * 2];
    const float rstd = g_stats[plane * 2 + 1];
    const float* zp = g_z + (size_t)plane * PLANE;
    float* op = out + (size_t)plane * PLANE;
    const int cc = threadIdx.x & 31;
    const int r0 = threadIdx.x >> 5;
#pragma unroll
    for (int k = 0; k < 4; ++k) {
        int rr = r0 + k * 8;
        s[rr][cc] = zp[(wb + rr) * HW + hb + cc];
    }
    __syncthreads();
#pragma unroll
    for (int k = 0; k < 4; ++k) {
        int rr = r0 + k * 8;
        op[(hb + rr) * HW + wb + cc] = (s[cc][rr] - mean) * rstd;
    }
}

// ---------------------------------------------------------------------------
extern "C" void kernel_launch(void* const* d_in, const int* in_sizes, int n_in,
                              void* d_out, int out_size) {
    const float* x       = (const float*)d_in[0];
    const float* filters = (const float*)d_in[1];
    const float* w1      = (const float*)d_in[2];
    float* out = (float*)d_out;

    cudaFuncSetAttribute(gabor_mma_kernel, cudaFuncAttributeMaxDynamicSharedMemorySize, SMEM_GABOR);
    cudaFuncSetAttribute(mix_kernel,       cudaFuncAttributeMaxDynamicSharedMemorySize, SMEM_MIX);

    gabor_mma_kernel<<<dim3(32, 128), 256, SMEM_GABOR>>>(x, filters);
    mix_kernel<<<dim3(32, 4), 256, SMEM_MIX>>>(w1);
    stats_kernel<<<128, 256>>>();
    norm_kernel<<<dim3(16, 128), 256>>>(out);
}

// round 15
// speedup vs baseline: 1.7813x; 1.4135x over previous
#include <cuda_runtime.h>
#include <cstdint>
#include <math.h>

#define KK     15
#define HW     128
#define PLANE  16384
#define CIN    768
#define NSO    24
#define NF     48          // filters (N dim)
#define RT     2           // output rows per segment
#define NSEG   16          // segments per CTA -> 32 rows per CTA
#define ROWS_CTA (RT*NSEG) // 32
#define NCHTOT (ROWS_CTA + 14)  // 46 input rows / A chunks per CTA
#define ARING  20          // TMEM A ring slots (16 cols each)

// ---- smem layout (bytes) for tcgen05 path ----
#define SM_TMEM   0
#define SM_MBAR   64                  // 16 mbarriers x 8B
#define SM_B      1024                // 15 B-slots x 6144B (48 rows x 128B, SW128)
#define SLOT_BF   6144
#define SM_X      (SM_B + 15*SLOT_BF) // 93184: 46 x-rows x 128 floats
#define SMEM_GABOR 116864             // 93184 + 23552 + pad

// TMEM: D buf0 @0 (2x48), D buf1 @96 (2x48), A ring @192 + slot*16 (320) = 512
#define TM_A0  192
#define TM_DSTRIDE 48

// idesc: dfmt=F32(1)<<4 | afmt=TF32(2)<<7 | bfmt=TF32(2)<<10 | (N/8)<<17 | (M/16)<<24
#define IDESC_TF32 ((1u<<4) | (2u<<7) | (2u<<10) | ((NF/8)<<17) | ((128/16)<<24))

#if defined(__CUDA_ARCH__) && (defined(__CUDA_ARCH_FEAT_SM103_ALL) || defined(__CUDA_ARCH_SPECIFIC__))
#define HAS_TCGEN05 1
#else
#define HAS_TCGEN05 0
#endif

typedef unsigned long long u64;

// Scratch (.bss)
__device__ float g_mag[(size_t)4 * CIN * PLANE];   // [b][c*24+so][y*128+x]
__device__ float g_z[(size_t)128 * PLANE];
__device__ float g_stats[256];

// ---------------- portable helpers ----------------
__device__ __forceinline__ u64 splat(float v) {
    u64 r; asm("mov.b64 %0, {%1,%1};" : "=l"(r) : "f"(v)); return r;
}
__device__ __forceinline__ void fma2(u64& d, u64 a, u64 b) {
    asm("fma.rn.f32x2 %0, %1, %2, %0;" : "+l"(d) : "l"(a), "l"(b));
}
__device__ __forceinline__ void upk2(u64 v, float& lo, float& hi) {
    asm("mov.b64 {%0,%1}, %2;" : "=f"(lo), "=f"(hi) : "l"(v));
}

#if HAS_TCGEN05
// ---------------- sm_103a-only helpers ----------------
__device__ __forceinline__ uint32_t smem_u32(const void* p) {
    uint32_t a;
    asm("{ .reg .u64 t; cvta.to.shared.u64 t, %1; cvt.u32.u64 %0, t; }" : "=r"(a) : "l"(p));
    return a;
}
__device__ __forceinline__ uint32_t elect1() {
    uint32_t p;
    asm volatile("{ .reg .pred p; elect.sync _|p, 0xFFFFFFFF; selp.b32 %0,1,0,p; }" : "=r"(p));
    return p;
}
__device__ __forceinline__ float tf32r(float v) {
    uint32_t r; asm("cvt.rna.tf32.f32 %0, %1;" : "=r"(r) : "f"(v));
    return __uint_as_float(r);
}
#define SWZ(o) ((o) ^ ((((uint32_t)(o)) >> 3) & 0x70))

static __device__ __forceinline__ uint64_t mkdesc(uint32_t addr) {
    const uint64_t base = (uint64_t(2) << 61) | (uint64_t(1) << 46)
                        | (uint64_t(64) << 32) | (uint64_t(1) << 16);  // SW128
    return base | ((uint64_t)(addr >> 4) & 0x3FFF);
}
__device__ __forceinline__ void tmem_alloc(uint32_t smem_addr, uint32_t ncols) {
    asm volatile("tcgen05.alloc.cta_group::1.sync.aligned.shared::cta.b32 [%0], %1;"
                 :: "r"(smem_addr), "r"(ncols) : "memory");
}
__device__ __forceinline__ void tmem_relinq() {
    asm volatile("tcgen05.relinquish_alloc_permit.cta_group::1.sync.aligned;");
}
__device__ __forceinline__ void tmem_dealloc(uint32_t tmem, uint32_t ncols) {
    asm volatile("tcgen05.dealloc.cta_group::1.sync.aligned.b32 %0, %1;" :: "r"(tmem), "r"(ncols));
}
__device__ __forceinline__ void mbar_init(uint32_t a, uint32_t cnt) {
    asm volatile("mbarrier.init.shared.b64 [%0], %1;" :: "r"(a), "r"(cnt) : "memory");
}
__device__ __forceinline__ void mbar_inval(uint32_t a) {
    asm volatile("mbarrier.inval.shared.b64 [%0];" :: "r"(a) : "memory");
}
__device__ __forceinline__ void mbar_wait(uint32_t a, uint32_t par) {
    uint32_t done;
    asm volatile("{ .reg .pred p; mbarrier.try_wait.parity.acquire.cta.shared::cta.b64 p, [%1], %2;"
                 " selp.b32 %0,1,0,p; }" : "=r"(done) : "r"(a), "r"(par) : "memory");
    if (!done) {
        asm volatile("{ .reg .pred P1; WL_%=: mbarrier.try_wait.parity.acquire.cta.shared::cta.b64 P1, [%0], %1, 0x989680;"
                     " @P1 bra.uni WD_%=; bra.uni WL_%=; WD_%=: }" :: "r"(a), "r"(par) : "memory");
    }
}
__device__ __forceinline__ void mma_commit(uint32_t mbar) {
    asm volatile("tcgen05.commit.cta_group::1.mbarrier::arrive::one.shared::cluster.b64 [%0];"
                 :: "r"(mbar) : "memory");
}
// TS form: A in TMEM, B via SMEM descriptor
__device__ __forceinline__ void mma_tf32_ts(uint32_t d, uint32_t a, uint64_t bd, uint32_t en) {
    asm volatile("{ .reg .pred p; setp.ne.u32 p, %4, 0;"
                 " tcgen05.mma.cta_group::1.kind::tf32 [%0], [%1], %2, %3, {%5,%5,%5,%5}, p; }"
                 :: "r"(d), "r"(a), "l"(bd), "r"(IDESC_TF32), "r"(en), "r"(0u) : "memory");
}
__device__ __forceinline__ void fence_async_shared() {
    asm volatile("fence.proxy.async.shared::cta;" ::: "memory");
}
__device__ __forceinline__ void tc_fence_before() {
    asm volatile("tcgen05.fence::before_thread_sync;" ::: "memory");
}
__device__ __forceinline__ void tc_fence_after() {
    asm volatile("tcgen05.fence::after_thread_sync;" ::: "memory");
}
__device__ __forceinline__ void tc_wait_st() {
    asm volatile("tcgen05.wait::st.sync.aligned;" ::: "memory");
}
__device__ __forceinline__ void tc_wait_ld() {
    asm volatile("tcgen05.wait::ld.sync.aligned;" ::: "memory");
}
__device__ __forceinline__ void sttm_x16(uint32_t a, const uint32_t* r) {
    asm volatile("tcgen05.st.sync.aligned.32x32b.x16.b32 [%0], "
        "{%1,%2,%3,%4,%5,%6,%7,%8,%9,%10,%11,%12,%13,%14,%15,%16};"
        :: "r"(a),
           "r"(r[0]),"r"(r[1]),"r"(r[2]),"r"(r[3]),"r"(r[4]),"r"(r[5]),"r"(r[6]),"r"(r[7]),
           "r"(r[8]),"r"(r[9]),"r"(r[10]),"r"(r[11]),"r"(r[12]),"r"(r[13]),"r"(r[14]),"r"(r[15])
        : "memory");
}
__device__ __forceinline__ void ldtm_x16(uint32_t* r, uint32_t a) {
    asm volatile("tcgen05.ld.sync.aligned.32x32b.x16.b32 "
        "{%0,%1,%2,%3,%4,%5,%6,%7,%8,%9,%10,%11,%12,%13,%14,%15}, [%16];"
        : "=r"(r[0]),"=r"(r[1]),"=r"(r[2]),"=r"(r[3]),"=r"(r[4]),"=r"(r[5]),"=r"(r[6]),"=r"(r[7]),
          "=r"(r[8]),"=r"(r[9]),"=r"(r[10]),"=r"(r[11]),"=r"(r[12]),"=r"(r[13]),"=r"(r[14]),"=r"(r[15])
        : "r"(a));
}

// im2col chunk builder: A rounded once to tf32 (hi only), 16 cols per chunk
__device__ __forceinline__ void build_chunk(char* smem, uint32_t tmem_a, int ci, int wid, int lid) {
    const float* xr = (const float*)(smem + SM_X) + ci * HW;
    const int xpos = (wid << 5) + lid;
    uint32_t regs[16];
#pragma unroll
    for (int dx = 0; dx < 16; ++dx) {
        int sx = xpos + dx - 7;
        float v = (dx < 15 && sx >= 0 && sx < HW) ? xr[sx] : 0.f;
        regs[dx] = __float_as_uint(tf32r(v));
    }
    sttm_x16(tmem_a + ((uint32_t)wid << 21), regs);
}
// Filters for one dy into SMEM (SW128): cols 0-15 hi(tf32), 16-31 lo(residual tf32)
__device__ __forceinline__ void build_filt(char* smem, int boff, const float* __restrict__ filters,
                                           int dy, int t) {
    for (int i = t; i < NF * 32; i += 128) {
        int f = i >> 5, col = i & 31, dx = col & 15;
        float v = (dx < 15) ? filters[(f >> 1) * 450 + (f & 1) * 225 + dy * 15 + dx] : 0.f;
        float hi = tf32r(v);
        float val = (col >= 16) ? tf32r(v - hi) : hi;
        *(float*)(smem + boff + SWZ(f * 128 + col * 4)) = val;
    }
}
#endif  // HAS_TCGEN05

// ---------------------------------------------------------------------------
// Kernel A: Gabor conv + magnitude.
// sm_103a: tcgen05 tf32 TS implicit GEMM, 2-term D = Ahi x (Bhi+Blo).
// SEGMENT-PIPELINED: 1 CTA = 32 output rows = 16 segments of 2 rows.
// B built once; per segment: build 2 A chunks (ring-20), issue 120 MMAs,
// commit(seg); wait(seg-2)+epilogue(seg-2) overlap the two in-flight segments.
// D double-buffered (2 x 96 TMEM cols). grid (4, 128), 256 thr, occ 1.
// ---------------------------------------------------------------------------
__global__ __launch_bounds__(256, 1)
void gabor_mma_kernel(const float* __restrict__ x, const float* __restrict__ filters) {
#if HAS_TCGEN05
    extern __shared__ char smem[];
    const uint32_t sb = smem_u32(smem);
    const int tid = threadIdx.x, wid = tid >> 5, lid = tid & 31;
    const int plane = blockIdx.y;
    const int y0 = blockIdx.x * ROWS_CTA;
    const int b = plane >> 5, c = plane & 31;

    // prologue (pre-alloc): stage 46 x rows, init 16 mbarriers, build all B
    const float* xp = x + (size_t)plane * PLANE;
    float* xs = (float*)(smem + SM_X);
    for (int i = tid; i < NCHTOT * HW; i += 256) {
        int rr = i >> 7, cc = i & 127;
        int gy = y0 + rr - 7;
        xs[i] = (gy >= 0 && gy < HW) ? xp[gy * HW + cc] : 0.f;
    }
    if (tid == 0)
        for (int i = 0; i < NSEG; ++i) mbar_init(sb + SM_MBAR + i * 8, 1);
    if (wid >= 4)
        for (int dy = 0; dy < KK; ++dy)
            build_filt(smem, SM_B + dy * SLOT_BF, filters, dy, tid - 128);
    __syncthreads();

    if (wid == 0) tmem_alloc(sb + SM_TMEM, 512);
    __syncthreads();
    uint32_t tmem;
    asm volatile("ld.shared.b32 %0, [%1];" : "=r"(tmem) : "r"(sb + SM_TMEM));
    if (wid == 0) tmem_relinq();

    // prebuild A chunks 0..15 (segment 0 window) into ring slots 0..15
    if (wid < 4) {
        for (int ci = 0; ci < 16; ++ci)
            build_chunk(smem, tmem + TM_A0 + (ci % ARING) * 16, ci, wid, lid);
        tc_wait_st();
    }

    const int sub = wid & 3;
    const int xc = sub * 32 + lid;
    const size_t mbase = ((size_t)b * CIN + (size_t)c * NSO) * PLANE + xc;
    const int er = wid >> 2;   // epilogue tile: warps 0-3 -> r=0, 4-7 -> r=1

    for (int s = 0; s < NSEG; ++s) {
        // drain segment s-2: frees D buffer s&1 and ring slots for build below
        if (s >= 2) {
            mbar_wait(sb + SM_MBAR + (s - 2) * 8, 0);
            tc_fence_after();
            const int t = s - 2;
            uint32_t rg[48];
            uint32_t dbase = tmem + (t & 1) * 96 + er * TM_DSTRIDE;
            ldtm_x16(rg,      dbase);
            ldtm_x16(rg + 16, dbase + 16);
            ldtm_x16(rg + 32, dbase + 32);
            tc_wait_ld();
            const int y = y0 + t * RT + er;
#pragma unroll
            for (int so = 0; so < NSO; ++so) {
                float re = __uint_as_float(rg[2 * so]);
                float im = __uint_as_float(rg[2 * so + 1]);
                g_mag[mbase + (size_t)so * PLANE + (size_t)y * HW] = sqrtf(re * re + im * im);
            }
        }
        // build next segment's 2 A chunks (slots last used by segment s-2)
        if (wid < 4 && s + 1 < NSEG) {
#pragma unroll
            for (int j = 0; j < 2; ++j) {
                int ci = 2 * s + 16 + j;
                build_chunk(smem, tmem + TM_A0 + (ci % ARING) * 16, ci, wid, lid);
            }
            tc_wait_st();
        }
        tc_fence_before();
        fence_async_shared();
        __syncthreads();
        // issue segment s (chunks 2s..2s+15), commit
        if (wid == 0) {
            tc_fence_after();
            if (elect1()) {
                for (int dy = 0; dy < KK; ++dy) {
                    uint64_t bd = mkdesc(sb + SM_B + dy * SLOT_BF);
#pragma unroll
                    for (int r = 0; r < RT; ++r) {
                        uint32_t a = tmem + TM_A0 + ((2 * s + dy + r) % ARING) * 16;
                        uint32_t d = tmem + (s & 1) * 96 + r * TM_DSTRIDE;
                        mma_tf32_ts(d, a + 0, bd + 0, dy > 0);  // Ahi x Bhi, k0
                        mma_tf32_ts(d, a + 8, bd + 2, 1);       // Ahi x Bhi, k1
                        mma_tf32_ts(d, a + 0, bd + 4, 1);       // Ahi x Blo, k0
                        mma_tf32_ts(d, a + 8, bd + 6, 1);       // Ahi x Blo, k1
                    }
                }
                mma_commit(sb + SM_MBAR + s * 8);
            }
        }
    }
    // drain last two segments
    for (int t = NSEG - 2; t < NSEG; ++t) {
        mbar_wait(sb + SM_MBAR + t * 8, 0);
        tc_fence_after();
        uint32_t rg[48];
        uint32_t dbase = tmem + (t & 1) * 96 + er * TM_DSTRIDE;
        ldtm_x16(rg,      dbase);
        ldtm_x16(rg + 16, dbase + 16);
        ldtm_x16(rg + 32, dbase + 32);
        tc_wait_ld();
        const int y = y0 + t * RT + er;
#pragma unroll
        for (int so = 0; so < NSO; ++so) {
            float re = __uint_as_float(rg[2 * so]);
            float im = __uint_as_float(rg[2 * so + 1]);
            g_mag[mbase + (size_t)so * PLANE + (size_t)y * HW] = sqrtf(re * re + im * im);
        }
    }
    __syncthreads();
    if (tid == 0)
        for (int i = 0; i < NSEG; ++i) mbar_inval(sb + SM_MBAR + i * 8);
    __syncthreads();
    if (wid == 0) tmem_dealloc(tmem, 512);

#else  // ---------------- scalar FFMA2 fallback (non-arch-specific pass) -----
    extern __shared__ float smf[];
    float* fs = smf;                        // [225][48]
    float* xs = smf + 225 * NF;             // [46][144]
    const int XW = 144;
    const int tid = threadIdx.x;
    const int plane = blockIdx.y;
    const int y0 = blockIdx.x * ROWS_CTA;
    const int b = plane >> 5, c = plane & 31;

    for (int i = tid; i < 225 * NF; i += 256) {
        int tap = i / NF, f = i - tap * NF;
        fs[i] = filters[(f >> 1) * 450 + (f & 1) * 225 + tap];
    }
    const float* xp = x + (size_t)plane * PLANE;
    for (int i = tid; i < NCHTOT * XW; i += 256) {
        int rr = i / XW, cc = i - rr * XW;
        int gy = y0 + rr - 7, gx = cc - 7;
        xs[i] = (gy >= 0 && gy < HW && gx >= 0 && gx < HW) ? xp[gy * HW + gx] : 0.f;
    }
    __syncthreads();

    const int x0 = (tid & 63) * 2;
    const int ry4 = tid >> 6;               // 0..3
    for (int blk = 0; blk < ROWS_CTA / 4; ++blk) {
        const int ry = blk * 4 + ry4;
        const size_t mbase0 = ((size_t)b * CIN + (size_t)c * NSO) * PLANE
                            + (size_t)(y0 + ry) * HW + x0;
        for (int g = 0; g < 4; ++g) {
            u64 acc[2][6];
#pragma unroll
            for (int p = 0; p < 2; ++p)
#pragma unroll
                for (int s = 0; s < 6; ++s) acc[p][s] = 0ull;
            for (int dy = 0; dy < KK; ++dy) {
                const float* xr = xs + (ry + dy) * XW + x0;
                const float* wr = fs + dy * KK * NF + g * 12;
#pragma unroll
                for (int dx = 0; dx < KK; ++dx) {
                    const float* w = wr + dx * NF;
                    ulonglong2 wa = *(const ulonglong2*)(w);
                    ulonglong2 wb = *(const ulonglong2*)(w + 4);
                    ulonglong2 wc = *(const ulonglong2*)(w + 8);
                    u64 wp[6] = {wa.x, wa.y, wb.x, wb.y, wc.x, wc.y};
                    u64 xv[2] = {splat(xr[dx]), splat(xr[dx + 1])};
#pragma unroll
                    for (int p = 0; p < 2; ++p)
#pragma unroll
                        for (int s = 0; s < 6; ++s) fma2(acc[p][s], xv[p], wp[s]);
                }
            }
#pragma unroll
            for (int s = 0; s < 6; ++s) {
                float re0, im0, re1, im1;
                upk2(acc[0][s], re0, im0);
                upk2(acc[1][s], re1, im1);
                float2 m = make_float2(sqrtf(re0*re0 + im0*im0), sqrtf(re1*re1 + im1*im1));
                *(float2*)(g_mag + mbase0 + (size_t)(g * 6 + s) * PLANE) = m;
            }
        }
    }
#endif
}

// ---------------------------------------------------------------------------
// Kernel B: channel mix (FFMA2), bias dropped (cancels in instance norm)
// ---------------------------------------------------------------------------
static const int SMEM_MIX = CIN * 32 * 4;

__global__ __launch_bounds__(256, 2)
void mix_kernel(const float* __restrict__ w1) {
    extern __shared__ float w1s[];
    const int tid = threadIdx.x;
    for (int i = tid; i < CIN * 32; i += 256) {
        int j = i >> 5, o = i & 31;
        w1s[i] = w1[o * CIN + j];
    }
    __syncthreads();

    const int bb = blockIdx.y;
    const int q0 = blockIdx.x * 512 + tid * 2;
    const float* mp = g_mag + (size_t)bb * CIN * PLANE + q0;

    u64 acc[16][2];
#pragma unroll
    for (int op = 0; op < 16; ++op) { acc[op][0] = 0ull; acc[op][1] = 0ull; }

#pragma unroll 4
    for (int j = 0; j < CIN; ++j) {
        float2 m = *(const float2*)(mp + (size_t)j * PLANE);
        u64 mx = splat(m.x), my = splat(m.y);
        const ulonglong2* wrow = (const ulonglong2*)(w1s + j * 32);
#pragma unroll
        for (int q4 = 0; q4 < 8; ++q4) {
            ulonglong2 w2 = wrow[q4];
            fma2(acc[q4 * 2 + 0][0], mx, w2.x);
            fma2(acc[q4 * 2 + 0][1], my, w2.x);
            fma2(acc[q4 * 2 + 1][0], mx, w2.y);
            fma2(acc[q4 * 2 + 1][1], my, w2.y);
        }
    }
#pragma unroll
    for (int op = 0; op < 16; ++op) {
        float a0lo, a0hi, a1lo, a1hi;
        upk2(acc[op][0], a0lo, a0hi);
        upk2(acc[op][1], a1lo, a1hi);
        *(float2*)(g_z + (size_t)(bb * 32 + 2 * op)     * PLANE + q0) = make_float2(a0lo, a1lo);
        *(float2*)(g_z + (size_t)(bb * 32 + 2 * op + 1) * PLANE + q0) = make_float2(a0hi, a1hi);
    }
}

// ---------------------------------------------------------------------------
__global__ void stats_kernel() {
    const int plane = blockIdx.x;
    const float* zp = g_z + (size_t)plane * PLANE;
    const int tid = threadIdx.x;
    float s = 0.f, s2 = 0.f;
    for (int i = tid * 4; i < PLANE; i += 1024) {
        float4 v = *(const float4*)(zp + i);
        s  += v.x + v.y + v.z + v.w;
        s2 += v.x * v.x + v.y * v.y + v.z * v.z + v.w * v.w;
    }
    __shared__ float r1[256], r2[256];
    r1[tid] = s; r2[tid] = s2;
    __syncthreads();
    for (int st = 128; st > 0; st >>= 1) {
        if (tid < st) { r1[tid] += r1[tid + st]; r2[tid] += r2[tid + st]; }
        __syncthreads();
    }
    if (tid == 0) {
        float mean = r1[0] * (1.f / PLANE);
        float var  = r2[0] * (1.f / PLANE) - mean * mean;
        g_stats[plane * 2]     = mean;
        g_stats[plane * 2 + 1] = rsqrtf(var + 1e-5f);
    }
}

__global__ void norm_kernel(float* __restrict__ out) {
    __shared__ float s[32][33];
    const int plane = blockIdx.y;
    const int tile  = blockIdx.x;
    const int hb = (tile >> 2) * 32, wb = (tile & 3) * 32;
    const float mean = g_stats[plane * 2];
    const float rstd = g_stats[plane * 2 + 1];
    const float* zp = g_z + (size_t)plane * PLANE;
    float* op = out + (size_t)plane * PLANE;
    const int cc = threadIdx.x & 31;
    const int r0 = threadIdx.x >> 5;
#pragma unroll
    for (int k = 0; k < 4; ++k) {
        int rr = r0 + k * 8;
        s[rr][cc] = zp[(wb + rr) * HW + hb + cc];
    }
    __syncthreads();
#pragma unroll
    for (int k = 0; k < 4; ++k) {
        int rr = r0 + k * 8;
        op[(hb + rr) * HW + wb + cc] = (s[cc][rr] - mean) * rstd;
    }
}

// ---------------------------------------------------------------------------
extern "C" void kernel_launch(void* const* d_in, const int* in_sizes, int n_in,
                              void* d_out, int out_size) {
    const float* x       = (const float*)d_in[0];
    const float* filters = (const float*)d_in[1];
    const float* w1      = (const float*)d_in[2];
    float* out = (float*)d_out;

    cudaFuncSetAttribute(gabor_mma_kernel, cudaFuncAttributeMaxDynamicSharedMemorySize, SMEM_GABOR);
    cudaFuncSetAttribute(mix_kernel,       cudaFuncAttributeMaxDynamicSharedMemorySize, SMEM_MIX);

    gabor_mma_kernel<<<dim3(HW / ROWS_CTA, 128), 256, SMEM_GABOR>>>(x, filters);
    mix_kernel<<<dim3(32, 4), 256, SMEM_MIX>>>(w1);
    stats_kernel<<<128, 256>>>();
    norm_kernel<<<dim3(16, 128), 256>>>(out);
}

// round 17
// speedup vs baseline: 1.9717x; 1.1069x over previous
#include <cuda_runtime.h>
#include <cstdint>
#include <math.h>

#define KK     15
#define HW     128
#define PLANE  16384
#define CIN    768
#define NSO    24
#define NF     48          // filters (N dim)
#define RT     2           // output rows per segment
#define NSEG   16          // segments per CTA -> 32 rows per CTA
#define ROWS_CTA (RT*NSEG) // 32
#define NCHTOT (ROWS_CTA + 14)  // 46 input rows / A chunks per CTA
#define ARING  20          // TMEM A ring slots (16 cols each)

// ---- smem layout (bytes) for tcgen05 path ----
#define SM_TMEM   0
#define SM_MBAR   64                  // 16 mbarriers x 8B
#define SM_B      1024                // 15 B-slots x 6144B (48 rows x 128B, SW128)
#define SLOT_BF   6144
#define SM_X      (SM_B + 15*SLOT_BF) // 93184: 46 x-rows x 128 floats
#define SMEM_GABOR 116864             // 93184 + 23552 + pad

// TMEM: D buf0 @0 (2x48), D buf1 @96 (2x48), A ring @192 + slot*16 (320) = 512
#define TM_A0  192
#define TM_DSTRIDE 48

// idesc: dfmt=F32(1)<<4 | afmt=TF32(2)<<7 | bfmt=TF32(2)<<10 | (N/8)<<17 | (M/16)<<24
#define IDESC_TF32 ((1u<<4) | (2u<<7) | (2u<<10) | ((NF/8)<<17) | ((128/16)<<24))

#if defined(__CUDA_ARCH__) && (defined(__CUDA_ARCH_FEAT_SM103_ALL) || defined(__CUDA_ARCH_SPECIFIC__))
#define HAS_TCGEN05 1
#else
#define HAS_TCGEN05 0
#endif

typedef unsigned long long u64;

// Scratch (.bss)
__device__ float g_mag[(size_t)4 * CIN * PLANE];   // [b][c*24+so][y*128+x]
__device__ float g_z[(size_t)128 * PLANE];
__device__ float g_stats[256];

// ---------------- portable helpers ----------------
__device__ __forceinline__ u64 splat(float v) {
    u64 r; asm("mov.b64 %0, {%1,%1};" : "=l"(r) : "f"(v)); return r;
}
__device__ __forceinline__ void fma2(u64& d, u64 a, u64 b) {
    asm("fma.rn.f32x2 %0, %1, %2, %0;" : "+l"(d) : "l"(a), "l"(b));
}
__device__ __forceinline__ void upk2(u64 v, float& lo, float& hi) {
    asm("mov.b64 {%0,%1}, %2;" : "=f"(lo), "=f"(hi) : "l"(v));
}

#if HAS_TCGEN05
// ---------------- sm_103a-only helpers ----------------
__device__ __forceinline__ uint32_t smem_u32(const void* p) {
    uint32_t a;
    asm("{ .reg .u64 t; cvta.to.shared.u64 t, %1; cvt.u32.u64 %0, t; }" : "=r"(a) : "l"(p));
    return a;
}
__device__ __forceinline__ uint32_t elect1() {
    uint32_t p;
    asm volatile("{ .reg .pred p; elect.sync _|p, 0xFFFFFFFF; selp.b32 %0,1,0,p; }" : "=r"(p));
    return p;
}
__device__ __forceinline__ float tf32r(float v) {
    uint32_t r; asm("cvt.rna.tf32.f32 %0, %1;" : "=r"(r) : "f"(v));
    return __uint_as_float(r);
}
#define SWZ(o) ((o) ^ ((((uint32_t)(o)) >> 3) & 0x70))

static __device__ __forceinline__ uint64_t mkdesc(uint32_t addr) {
    const uint64_t base = (uint64_t(2) << 61) | (uint64_t(1) << 46)
                        | (uint64_t(64) << 32) | (uint64_t(1) << 16);  // SW128
    return base | ((uint64_t)(addr >> 4) & 0x3FFF);
}
__device__ __forceinline__ void tmem_alloc(uint32_t smem_addr, uint32_t ncols) {
    asm volatile("tcgen05.alloc.cta_group::1.sync.aligned.shared::cta.b32 [%0], %1;"
                 :: "r"(smem_addr), "r"(ncols) : "memory");
}
__device__ __forceinline__ void tmem_relinq() {
    asm volatile("tcgen05.relinquish_alloc_permit.cta_group::1.sync.aligned;");
}
__device__ __forceinline__ void tmem_dealloc(uint32_t tmem, uint32_t ncols) {
    asm volatile("tcgen05.dealloc.cta_group::1.sync.aligned.b32 %0, %1;" :: "r"(tmem), "r"(ncols));
}
__device__ __forceinline__ void mbar_init(uint32_t a, uint32_t cnt) {
    asm volatile("mbarrier.init.shared.b64 [%0], %1;" :: "r"(a), "r"(cnt) : "memory");
}
__device__ __forceinline__ void mbar_inval(uint32_t a) {
    asm volatile("mbarrier.inval.shared.b64 [%0];" :: "r"(a) : "memory");
}
__device__ __forceinline__ void mbar_wait(uint32_t a, uint32_t par) {
    uint32_t done;
    asm volatile("{ .reg .pred p; mbarrier.try_wait.parity.acquire.cta.shared::cta.b64 p, [%1], %2;"
                 " selp.b32 %0,1,0,p; }" : "=r"(done) : "r"(a), "r"(par) : "memory");
    if (!done) {
        asm volatile("{ .reg .pred P1; WL_%=: mbarrier.try_wait.parity.acquire.cta.shared::cta.b64 P1, [%0], %1, 0x989680;"
                     " @P1 bra.uni WD_%=; bra.uni WL_%=; WD_%=: }" :: "r"(a), "r"(par) : "memory");
    }
}
__device__ __forceinline__ void mma_commit(uint32_t mbar) {
    asm volatile("tcgen05.commit.cta_group::1.mbarrier::arrive::one.shared::cluster.b64 [%0];"
                 :: "r"(mbar) : "memory");
}
// TS form: A in TMEM, B via SMEM descriptor
__device__ __forceinline__ void mma_tf32_ts(uint32_t d, uint32_t a, uint64_t bd, uint32_t en) {
    asm volatile("{ .reg .pred p; setp.ne.u32 p, %4, 0;"
                 " tcgen05.mma.cta_group::1.kind::tf32 [%0], [%1], %2, %3, {%5,%5,%5,%5}, p; }"
                 :: "r"(d), "r"(a), "l"(bd), "r"(IDESC_TF32), "r"(en), "r"(0u) : "memory");
}
__device__ __forceinline__ void fence_async_shared() {
    asm volatile("fence.proxy.async.shared::cta;" ::: "memory");
}
__device__ __forceinline__ void tc_fence_before() {
    asm volatile("tcgen05.fence::before_thread_sync;" ::: "memory");
}
__device__ __forceinline__ void tc_fence_after() {
    asm volatile("tcgen05.fence::after_thread_sync;" ::: "memory");
}
__device__ __forceinline__ void tc_wait_st() {
    asm volatile("tcgen05.wait::st.sync.aligned;" ::: "memory");
}
__device__ __forceinline__ void tc_wait_ld() {
    asm volatile("tcgen05.wait::ld.sync.aligned;" ::: "memory");
}
__device__ __forceinline__ void sttm_x16(uint32_t a, const uint32_t* r) {
    asm volatile("tcgen05.st.sync.aligned.32x32b.x16.b32 [%0], "
        "{%1,%2,%3,%4,%5,%6,%7,%8,%9,%10,%11,%12,%13,%14,%15,%16};"
        :: "r"(a),
           "r"(r[0]),"r"(r[1]),"r"(r[2]),"r"(r[3]),"r"(r[4]),"r"(r[5]),"r"(r[6]),"r"(r[7]),
           "r"(r[8]),"r"(r[9]),"r"(r[10]),"r"(r[11]),"r"(r[12]),"r"(r[13]),"r"(r[14]),"r"(r[15])
        : "memory");
}
__device__ __forceinline__ void ldtm_x16(uint32_t* r, uint32_t a) {
    asm volatile("tcgen05.ld.sync.aligned.32x32b.x16.b32 "
        "{%0,%1,%2,%3,%4,%5,%6,%7,%8,%9,%10,%11,%12,%13,%14,%15}, [%16];"
        : "=r"(r[0]),"=r"(r[1]),"=r"(r[2]),"=r"(r[3]),"=r"(r[4]),"=r"(r[5]),"=r"(r[6]),"=r"(r[7]),
          "=r"(r[8]),"=r"(r[9]),"=r"(r[10]),"=r"(r[11]),"=r"(r[12]),"=r"(r[13]),"=r"(r[14]),"=r"(r[15])
        : "r"(a));
}

// im2col chunk builder: A rounded once to tf32 (hi only), 16 cols per chunk
__device__ __forceinline__ void build_chunk(char* smem, uint32_t tmem_a, int ci, int wid, int lid) {
    const float* xr = (const float*)(smem + SM_X) + ci * HW;
    const int xpos = (wid << 5) + lid;
    uint32_t regs[16];
#pragma unroll
    for (int dx = 0; dx < 16; ++dx) {
        int sx = xpos + dx - 7;
        float v = (dx < 15 && sx >= 0 && sx < HW) ? xr[sx] : 0.f;
        regs[dx] = __float_as_uint(tf32r(v));
    }
    sttm_x16(tmem_a + ((uint32_t)wid << 21), regs);
}
// Filters for one dy into SMEM (SW128): hi(tf32) only, cols 0-15. Threads 128-255.
__device__ __forceinline__ void build_filt(char* smem, int boff, const float* __restrict__ filters,
                                           int dy, int t) {
    for (int i = t; i < NF * 16; i += 128) {
        int f = i >> 4, dx = i & 15;
        float v = (dx < 15) ? filters[(f >> 1) * 450 + (f & 1) * 225 + dy * 15 + dx] : 0.f;
        *(float*)(smem + boff + SWZ(f * 128 + dx * 4)) = tf32r(v);
    }
}
#endif  // HAS_TCGEN05

// ---------------------------------------------------------------------------
// Kernel A: Gabor conv + magnitude.
// sm_103a: tcgen05 tf32 TS implicit GEMM, SINGLE-TERM: D = Ahi x Bhi
// (both operands rounded once to tf32; measured error each side ~3.3e-4).
// SEGMENT-PIPELINED (R15 base): 1 CTA = 32 rows = 16 segments of 2 rows.
// B built once; per segment: build 2 A chunks (ring-20), issue 60 MMAs,
// commit(seg); wait(seg-2)+epilogue(seg-2) overlap in-flight segments.
// D double-buffered (2 x 96 TMEM cols). grid (4, 128), 256 thr, occ 1.
// ---------------------------------------------------------------------------
__global__ __launch_bounds__(256, 1)
void gabor_mma_kernel(const float* __restrict__ x, const float* __restrict__ filters) {
#if HAS_TCGEN05
    extern __shared__ char smem[];
    const uint32_t sb = smem_u32(smem);
    const int tid = threadIdx.x, wid = tid >> 5, lid = tid & 31;
    const int plane = blockIdx.y;
    const int y0 = blockIdx.x * ROWS_CTA;
    const int b = plane >> 5, c = plane & 31;

    // prologue (pre-alloc): stage 46 x rows, init 16 mbarriers, build all B
    const float* xp = x + (size_t)plane * PLANE;
    float* xs = (float*)(smem + SM_X);
    for (int i = tid; i < NCHTOT * HW; i += 256) {
        int rr = i >> 7, cc = i & 127;
        int gy = y0 + rr - 7;
        xs[i] = (gy >= 0 && gy < HW) ? xp[gy * HW + cc] : 0.f;
    }
    if (tid == 0)
        for (int i = 0; i < NSEG; ++i) mbar_init(sb + SM_MBAR + i * 8, 1);
    if (wid >= 4)
        for (int dy = 0; dy < KK; ++dy)
            build_filt(smem, SM_B + dy * SLOT_BF, filters, dy, tid - 128);
    __syncthreads();

    if (wid == 0) tmem_alloc(sb + SM_TMEM, 512);
    __syncthreads();
    uint32_t tmem;
    asm volatile("ld.shared.b32 %0, [%1];" : "=r"(tmem) : "r"(sb + SM_TMEM));
    if (wid == 0) tmem_relinq();

    // prebuild A chunks 0..15 (segment 0 window) into ring slots 0..15
    if (wid < 4) {
        for (int ci = 0; ci < 16; ++ci)
            build_chunk(smem, tmem + TM_A0 + (ci % ARING) * 16, ci, wid, lid);
        tc_wait_st();
    }

    const int sub = wid & 3;
    const int xc = sub * 32 + lid;
    const size_t mbase = ((size_t)b * CIN + (size_t)c * NSO) * PLANE + xc;
    const int er = wid >> 2;   // epilogue tile: warps 0-3 -> r=0, 4-7 -> r=1

    for (int s = 0; s < NSEG; ++s) {
        // drain segment s-2: frees D buffer s&1 and ring slots for build below
        if (s >= 2) {
            mbar_wait(sb + SM_MBAR + (s - 2) * 8, 0);
            tc_fence_after();
            const int t = s - 2;
            uint32_t rg[48];
            uint32_t dbase = tmem + (t & 1) * 96 + er * TM_DSTRIDE;
            ldtm_x16(rg,      dbase);
            ldtm_x16(rg + 16, dbase + 16);
            ldtm_x16(rg + 32, dbase + 32);
            tc_wait_ld();
            const int y = y0 + t * RT + er;
#pragma unroll
            for (int so = 0; so < NSO; ++so) {
                float re = __uint_as_float(rg[2 * so]);
                float im = __uint_as_float(rg[2 * so + 1]);
                g_mag[mbase + (size_t)so * PLANE + (size_t)y * HW] = sqrtf(re * re + im * im);
            }
        }
        // build next segment's 2 A chunks (slots last used by segment s-2)
        if (wid < 4 && s + 1 < NSEG) {
#pragma unroll
            for (int j = 0; j < 2; ++j) {
                int ci = 2 * s + 16 + j;
                build_chunk(smem, tmem + TM_A0 + (ci % ARING) * 16, ci, wid, lid);
            }
            tc_wait_st();
        }
        tc_fence_before();
        fence_async_shared();
        __syncthreads();
        // issue segment s (chunks 2s..2s+15): 60 MMAs, commit
        if (wid == 0) {
            tc_fence_after();
            if (elect1()) {
                for (int dy = 0; dy < KK; ++dy) {
                    uint64_t bd = mkdesc(sb + SM_B + dy * SLOT_BF);
#pragma unroll
                    for (int r = 0; r < RT; ++r) {
                        uint32_t a = tmem + TM_A0 + ((2 * s + dy + r) % ARING) * 16;
                        uint32_t d = tmem + (s & 1) * 96 + r * TM_DSTRIDE;
                        mma_tf32_ts(d, a + 0, bd + 0, dy > 0);  // Ahi x Bhi, k0
                        mma_tf32_ts(d, a + 8, bd + 2, 1);       // Ahi x Bhi, k1
                    }
                }
                mma_commit(sb + SM_MBAR + s * 8);
            }
        }
    }
    // drain last two segments
    for (int t = NSEG - 2; t < NSEG; ++t) {
        mbar_wait(sb + SM_MBAR + t * 8, 0);
        tc_fence_after();
        uint32_t rg[48];
        uint32_t dbase = tmem + (t & 1) * 96 + er * TM_DSTRIDE;
        ldtm_x16(rg,      dbase);
        ldtm_x16(rg + 16, dbase + 16);
        ldtm_x16(rg + 32, dbase + 32);
        tc_wait_ld();
        const int y = y0 + t * RT + er;
#pragma unroll
        for (int so = 0; so < NSO; ++so) {
            float re = __uint_as_float(rg[2 * so]);
            float im = __uint_as_float(rg[2 * so + 1]);
            g_mag[mbase + (size_t)so * PLANE + (size_t)y * HW] = sqrtf(re * re + im * im);
        }
    }
    __syncthreads();
    if (tid == 0)
        for (int i = 0; i < NSEG; ++i) mbar_inval(sb + SM_MBAR + i * 8);
    __syncthreads();
    if (wid == 0) tmem_dealloc(tmem, 512);

#else  // ---------------- scalar FFMA2 fallback (non-arch-specific pass) -----
    extern __shared__ float smf[];
    float* fs = smf;                        // [225][48]
    float* xs = smf + 225 * NF;             // [46][144]
    const int XW = 144;
    const int tid = threadIdx.x;
    const int plane = blockIdx.y;
    const int y0 = blockIdx.x * ROWS_CTA;
    const int b = plane >> 5, c = plane & 31;

    for (int i = tid; i < 225 * NF; i += 256) {
        int tap = i / NF, f = i - tap * NF;
        fs[i] = filters[(f >> 1) * 450 + (f & 1) * 225 + tap];
    }
    const float* xp = x + (size_t)plane * PLANE;
    for (int i = tid; i < NCHTOT * XW; i += 256) {
        int rr = i / XW, cc = i - rr * XW;
        int gy = y0 + rr - 7, gx = cc - 7;
        xs[i] = (gy >= 0 && gy < HW && gx >= 0 && gx < HW) ? xp[gy * HW + gx] : 0.f;
    }
    __syncthreads();

    const int x0 = (tid & 63) * 2;
    const int ry4 = tid >> 6;               // 0..3
    for (int blk = 0; blk < ROWS_CTA / 4; ++blk) {
        const int ry = blk * 4 + ry4;
        const size_t mbase0 = ((size_t)b * CIN + (size_t)c * NSO) * PLANE
                            + (size_t)(y0 + ry) * HW + x0;
        for (int g = 0; g < 4; ++g) {
            u64 acc[2][6];
#pragma unroll
            for (int p = 0; p < 2; ++p)
#pragma unroll
                for (int s = 0; s < 6; ++s) acc[p][s] = 0ull;
            for (int dy = 0; dy < KK; ++dy) {
                const float* xr = xs + (ry + dy) * XW + x0;
                const float* wr = fs + dy * KK * NF + g * 12;
#pragma unroll
                for (int dx = 0; dx < KK; ++dx) {
                    const float* w = wr + dx * NF;
                    ulonglong2 wa = *(const ulonglong2*)(w);
                    ulonglong2 wb = *(const ulonglong2*)(w + 4);
                    ulonglong2 wc = *(const ulonglong2*)(w + 8);
                    u64 wp[6] = {wa.x, wa.y, wb.x, wb.y, wc.x, wc.y};
                    u64 xv[2] = {splat(xr[dx]), splat(xr[dx + 1])};
#pragma unroll
                    for (int p = 0; p < 2; ++p)
#pragma unroll
                        for (int s = 0; s < 6; ++s) fma2(acc[p][s], xv[p], wp[s]);
                }
            }
#pragma unroll
            for (int s = 0; s < 6; ++s) {
                float re0, im0, re1, im1;
                upk2(acc[0][s], re0, im0);
                upk2(acc[1][s], re1, im1);
                float2 m = make_float2(sqrtf(re0*re0 + im0*im0), sqrtf(re1*re1 + im1*im1));
                *(float2*)(g_mag + mbase0 + (size_t)(g * 6 + s) * PLANE) = m;
            }
        }
    }
#endif
}

// ---------------------------------------------------------------------------
// Kernel B: channel mix (FFMA2), bias dropped (cancels in instance norm)
// ---------------------------------------------------------------------------
static const int SMEM_MIX = CIN * 32 * 4;

__global__ __launch_bounds__(256, 2)
void mix_kernel(const float* __restrict__ w1) {
    extern __shared__ float w1s[];
    const int tid = threadIdx.x;
    for (int i = tid; i < CIN * 32; i += 256) {
        int j = i >> 5, o = i & 31;
        w1s[i] = w1[o * CIN + j];
    }
    __syncthreads();

    const int bb = blockIdx.y;
    const int q0 = blockIdx.x * 512 + tid * 2;
    const float* mp = g_mag + (size_t)bb * CIN * PLANE + q0;

    u64 acc[16][2];
#pragma unroll
    for (int op = 0; op < 16; ++op) { acc[op][0] = 0ull; acc[op][1] = 0ull; }

#pragma unroll 4
    for (int j = 0; j < CIN; ++j) {
        float2 m = *(const float2*)(mp + (size_t)j * PLANE);
        u64 mx = splat(m.x), my = splat(m.y);
        const ulonglong2* wrow = (const ulonglong2*)(w1s + j * 32);
#pragma unroll
        for (int q4 = 0; q4 < 8; ++q4) {
            ulonglong2 w2 = wrow[q4];
            fma2(acc[q4 * 2 + 0][0], mx, w2.x);
            fma2(acc[q4 * 2 + 0][1], my, w2.x);
            fma2(acc[q4 * 2 + 1][0], mx, w2.y);
            fma2(acc[q4 * 2 + 1][1], my, w2.y);
        }
    }
#pragma unroll
    for (int op = 0; op < 16; ++op) {
        float a0lo, a0hi, a1lo, a1hi;
        upk2(acc[op][0], a0lo, a0hi);
        upk2(acc[op][1], a1lo, a1hi);
        *(float2*)(g_z + (size_t)(bb * 32 + 2 * op)     * PLANE + q0) = make_float2(a0lo, a1lo);
        *(float2*)(g_z + (size_t)(bb * 32 + 2 * op + 1) * PLANE + q0) = make_float2(a0hi, a1hi);
    }
}

// ---------------------------------------------------------------------------
__global__ void stats_kernel() {
    const int plane = blockIdx.x;
    const float* zp = g_z + (size_t)plane * PLANE;
    const int tid = threadIdx.x;
    float s = 0.f, s2 = 0.f;
    for (int i = tid * 4; i < PLANE; i += 1024) {
        float4 v = *(const float4*)(zp + i);
        s  += v.x + v.y + v.z + v.w;
        s2 += v.x * v.x + v.y * v.y + v.z * v.z + v.w * v.w;
    }
    __shared__ float r1[256], r2[256];
    r1[tid] = s; r2[tid] = s2;
    __syncthreads();
    for (int st = 128; st > 0; st >>= 1) {
        if (tid < st) { r1[tid] += r1[tid + st]; r2[tid] += r2[tid + st]; }
        __syncthreads();
    }
    if (tid == 0) {
        float mean = r1[0] * (1.f / PLANE);
        float var  = r2[0] * (1.f / PLANE) - mean * mean;
        g_stats[plane * 2]     = mean;
        g_stats[plane * 2 + 1] = rsqrtf(var + 1e-5f);
    }
}

__global__ void norm_kernel(float* __restrict__ out) {
    __shared__ float s[32][33];
    const int plane = blockIdx.y;
    const int tile  = blockIdx.x;
    const int hb = (tile >> 2) * 32, wb = (tile & 3) * 32;
    const float mean = g_stats[plane * 2];
    const float rstd = g_stats[plane * 2 + 1];
    const float* zp = g_z + (size_t)plane * PLANE;
    float* op = out + (size_t)plane * PLANE;
    const int cc = threadIdx.x & 31;
    const int r0 = threadIdx.x >> 5;
#pragma unroll
    for (int k = 0; k < 4; ++k) {
        int rr = r0 + k * 8;
        s[rr][cc] = zp[(wb + rr) * HW + hb + cc];
    }
    __syncthreads();
#pragma unroll
    for (int k = 0; k < 4; ++k) {
        int rr = r0 + k * 8;
        op[(hb + rr) * HW + wb + cc] = (s[cc][rr] - mean) * rstd;
    }
}

// ---------------------------------------------------------------------------
extern "C" void kernel_launch(void* const* d_in, const int* in_sizes, int n_in,
                              void* d_out, int out_size) {
    const float* x       = (const float*)d_in[0];
    const float* filters = (const float*)d_in[1];
    const float* w1      = (const float*)d_in[2];
    float* out = (float*)d_out;

    cudaFuncSetAttribute(gabor_mma_kernel, cudaFuncAttributeMaxDynamicSharedMemorySize, SMEM_GABOR);
    cudaFuncSetAttribute(mix_kernel,       cudaFuncAttributeMaxDynamicSharedMemorySize, SMEM_MIX);

    gabor_mma_kernel<<<dim3(HW / ROWS_CTA, 128), 256, SMEM_GABOR>>>(x, filters);
    mix_kernel<<<dim3(32, 4), 256, SMEM_MIX>>>(w1);
    stats_kernel<<<128, 256>>>();
    norm_kernel<<<dim3(16, 128), 256>>>(out);
}